// round 13
// baseline (speedup 1.0000x reference)
#include <cuda_runtime.h>
#include <cuda_fp16.h>
#include <cstdint>

// Problem constants
#define B_      8
#define D_      512
#define H_      8
#define HD_     64
#define L_NS_   64
#define L_S_    2048
#define L_TOT   2112
#define LS_OUT  512
#define LQ_     576
#define LQPAD   640

// Q scale: 1/sqrt(64) * log2(e)  (exp2 domain)
#define SCL 0.18033688011112042f

// Scratch (allocation-free device globals)
__device__ __half g_K[B_ * L_TOT * D_];
__device__ __half g_V[B_ * L_TOT * D_];
__device__ __half g_Q[B_ * LQPAD * D_];          // rows 576-639 stay zero
__device__ __half g_A[B_ * LQPAD * D_];          // attention out (fp16)
__device__ float  g_Part[3 * 4 * 64 * B_ * D_];
__device__ __half g_Xh[B_ * L_TOT * D_];         // fp16 x
__device__ __half g_Wh[4 * D_ * D_];             // fp16 wk_sw, wv_sw, wq_sw, out_w
__device__ __half g_PadH[B_ * L_S_];             // fp16 0/1 pad mask

#define WSZ ((size_t)D_ * D_)
#define PARTSZ ((size_t)4 * 64 * B_ * D_)

// ---------------------------------------------------------------------------
// Helpers
// ---------------------------------------------------------------------------
__device__ __forceinline__ uint32_t smem_u32(const void* p) {
    uint32_t a;
    asm("{ .reg .u64 t; cvta.to.shared.u64 t, %1; cvt.u32.u64 %0, t; }" : "=r"(a) : "l"(p));
    return a;
}
__device__ __forceinline__ uint32_t packh2(float a, float b) {
    __half2 h = __floats2half2_rn(a, b);
    return *(uint32_t*)&h;
}
__device__ __forceinline__ uint32_t h2exp2(uint32_t h) {
    uint32_t r; asm("ex2.approx.f16x2 %0, %1;" : "=r"(r) : "r"(h)); return r;
}
__device__ __forceinline__ void mma16(float4& d, const uint32_t a[4], uint32_t b0, uint32_t b1) {
    asm volatile(
        "mma.sync.aligned.m16n8k16.row.col.f32.f16.f16.f32 "
        "{%0,%1,%2,%3}, {%4,%5,%6,%7}, {%8,%9}, {%0,%1,%2,%3};"
        : "+f"(d.x), "+f"(d.y), "+f"(d.z), "+f"(d.w)
        : "r"(a[0]), "r"(a[1]), "r"(a[2]), "r"(a[3]), "r"(b0), "r"(b1));
}
__device__ __forceinline__ void ldsm4(uint32_t& r0, uint32_t& r1, uint32_t& r2, uint32_t& r3,
                                      uint32_t addr) {
    asm volatile("ldmatrix.sync.aligned.m8n8.x4.shared.b16 {%0,%1,%2,%3}, [%4];"
                 : "=r"(r0), "=r"(r1), "=r"(r2), "=r"(r3) : "r"(addr));
}
__device__ __forceinline__ void ldsm4t(uint32_t& r0, uint32_t& r1, uint32_t& r2, uint32_t& r3,
                                       uint32_t addr) {
    asm volatile("ldmatrix.sync.aligned.m8n8.x4.trans.shared.b16 {%0,%1,%2,%3}, [%4];"
                 : "=r"(r0), "=r"(r1), "=r"(r2), "=r"(r3) : "r"(addr));
}
__device__ __forceinline__ void cp16(uint32_t dst, const void* src) {
    asm volatile("cp.async.cg.shared.global [%0], [%1], 16;" :: "r"(dst), "l"(src));
}
#define CP_COMMIT() asm volatile("cp.async.commit_group;" ::: "memory")
#define CP_WAIT1()  asm volatile("cp.async.wait_group 1;" ::: "memory")

// ---------------------------------------------------------------------------
// Fused prep: x->fp16, 4 weights->fp16, pad->fp16
// ---------------------------------------------------------------------------
#define XN4L ((long)B_ * L_TOT * D_ / 4)

__global__ __launch_bounds__(256)
void prep_all(const float* __restrict__ x,
              const float* __restrict__ w0, const float* __restrict__ w1,
              const float* __restrict__ w2, const float* __restrict__ w3,
              const int* __restrict__ pad,
              __half* __restrict__ Xh, __half* __restrict__ Wh,
              __half* __restrict__ PadH) {
    long i = (long)blockIdx.x * 256 + threadIdx.x;
    if (i < XN4L) {
        float4 v = ((const float4*)x)[i];
        ((__half2*)Xh)[2 * i] = __floats2half2_rn(v.x, v.y);
        ((__half2*)Xh)[2 * i + 1] = __floats2half2_rn(v.z, v.w);
        return;
    }
    long j = i - XN4L;
    if (j < 262144) {
        int which = (int)(j >> 16);
        long off = j & 65535;
        const float* w = (which == 0) ? w0 : (which == 1) ? w1 : (which == 2) ? w2 : w3;
        float4 v = ((const float4*)w)[off];
        __half2* dst = (__half2*)(Wh + (size_t)which * WSZ);
        dst[2 * off] = __floats2half2_rn(v.x, v.y);
        dst[2 * off + 1] = __floats2half2_rn(v.z, v.w);
        return;
    }
    long k = j - 262144;
    if (k < (long)(B_ * L_S_ / 8)) {
        long base = k * 8;
#pragma unroll
        for (int q = 0; q < 8; ++q)
            PadH[base + q] = __int2half_rn(pad[base + q] ? 1 : 0);
    }
}

// ---------------------------------------------------------------------------
// Dense projection body, fp16 mma m16n8k16 + ldmatrix, 3-stage cp.async.
// ---------------------------------------------------------------------------
template <int MODE> __device__ __forceinline__ int arow_of(int mi) {
    if (MODE == 0) return (mi >> 11) * L_TOT + (mi & 2047);
    if (MODE == 1) return (mi >> 9) * L_TOT + 1536 + (mi & 511);
    return ((unsigned)mi / 576) * LQPAD + ((unsigned)mi % 576);
}
template <int MODE> __device__ __forceinline__ int crow_of(int mi) {
    if (MODE == 0) return (mi >> 11) * L_TOT + (mi & 2047);
    if (MODE == 1) return (mi >> 9) * LQPAD + (mi & 511);
    return mi;
}

#define PH_AS (128 * 40)
#define PH_WS (32 * 136)
#define PJ_SMEM (3 * (PH_AS + PH_WS) * 2)

template <int MODE, int RND, int PADV>
__device__ __forceinline__
void proj_body(char* smc, int m0, int n0,
               const __half* __restrict__ A, const __half* __restrict__ W,
               const float* __restrict__ bias, void* __restrict__ C,
               const int* __restrict__ pad) {
    const uint32_t as_u = smem_u32(smc);
    const uint32_t ws_u = as_u + 3 * PH_AS * 2;

    const int tid = threadIdx.x, lane = tid & 31;
    const int warp = tid >> 5, wm = warp >> 2, wn = warp & 3;
    const int g = lane >> 2, t4 = lane & 3;
    const int lt = lane >> 3, lr8 = lane & 7;

    const int ar = tid >> 2, aseg = (tid & 3) * 8;
    const __half* pA0 = A + (size_t)arow_of<MODE>(m0 + ar) * D_ + aseg;
    const __half* pA1 = A + (size_t)arow_of<MODE>(m0 + 64 + ar) * D_ + aseg;
    const int wr = tid >> 4, wseg = (tid & 15) * 8;
    const __half* pW = W + n0 + wseg;

    auto issue = [&](int c, int s) {
        const int k0 = c * 32;
        uint32_t ad = as_u + (uint32_t)(s * PH_AS) * 2;
        cp16(ad + (uint32_t)(ar * 40 + aseg) * 2, pA0 + k0);
        cp16(ad + (uint32_t)((ar + 64) * 40 + aseg) * 2, pA1 + k0);
        uint32_t wd = ws_u + (uint32_t)(s * PH_WS) * 2;
        cp16(wd + (uint32_t)(wr * 136 + wseg) * 2, pW + (size_t)(k0 + wr) * D_);
        cp16(wd + (uint32_t)((wr + 16) * 136 + wseg) * 2, pW + (size_t)(k0 + wr + 16) * D_);
    };

    float4 acc[4][4];
#pragma unroll
    for (int i = 0; i < 4; ++i)
#pragma unroll
        for (int j = 0; j < 4; ++j) acc[i][j] = make_float4(0.f, 0.f, 0.f, 0.f);

    issue(0, 0); CP_COMMIT();
    issue(1, 1); CP_COMMIT();

#pragma unroll 1
    for (int c = 0; c < 16; ++c) {
        const int s = c % 3;
        CP_WAIT1();
        __syncthreads();
        if (c + 2 < 16) issue(c + 2, (c + 2) % 3);
        CP_COMMIT();

        const uint32_t as_ = as_u + (uint32_t)(s * PH_AS) * 2;
        const uint32_t ws_ = ws_u + (uint32_t)(s * PH_WS) * 2;
#pragma unroll
        for (int kc = 0; kc < 2; ++kc) {
            uint32_t af[4][4], bf[4][2];
#pragma unroll
            for (int mi = 0; mi < 4; ++mi) {
                uint32_t addr = as_ +
                    (uint32_t)(((wm * 64 + mi * 16 + (lane & 15)) * 40) + kc * 16 + (lane >> 4) * 8) * 2;
                ldsm4(af[mi][0], af[mi][1], af[mi][2], af[mi][3], addr);
            }
#pragma unroll
            for (int pr = 0; pr < 2; ++pr) {
                uint32_t addr = ws_ +
                    (uint32_t)(((kc * 16 + (lt & 1) * 8 + lr8) * 136) + wn * 32 + (pr * 2 + (lt >> 1)) * 8) * 2;
                ldsm4t(bf[2 * pr][0], bf[2 * pr][1], bf[2 * pr + 1][0], bf[2 * pr + 1][1], addr);
            }
#pragma unroll
            for (int mi = 0; mi < 4; ++mi)
#pragma unroll
                for (int ni = 0; ni < 4; ++ni)
                    mma16(acc[mi][ni], af[mi], bf[ni][0], bf[ni][1]);
        }
    }

    float pm[4][2];
    if (PADV) {
#pragma unroll
        for (int mi = 0; mi < 4; ++mi) {
            int mr0 = m0 + wm * 64 + mi * 16 + g;
            int mr1 = mr0 + 8;
            pm[mi][0] = pad[(mr0 >> 11) * L_S_ + (mr0 & 2047)] ? 1.f : 0.f;
            pm[mi][1] = pad[(mr1 >> 11) * L_S_ + (mr1 & 2047)] ? 1.f : 0.f;
        }
    }

#pragma unroll
    for (int ni = 0; ni < 4; ++ni) {
        int col = n0 + wn * 32 + ni * 8 + 2 * t4;
        float2 bv = *(const float2*)(bias + col);
#pragma unroll
        for (int mi = 0; mi < 4; ++mi) {
            int r0 = crow_of<MODE>(m0 + wm * 64 + mi * 16 + g);
            int r1 = crow_of<MODE>(m0 + wm * 64 + mi * 16 + g + 8);
            float o0 = acc[mi][ni].x + bv.x, o1 = acc[mi][ni].y + bv.y;
            float o2 = acc[mi][ni].z + bv.x, o3 = acc[mi][ni].w + bv.y;
            if (PADV) { o0 *= pm[mi][0]; o1 *= pm[mi][0]; o2 *= pm[mi][1]; o3 *= pm[mi][1]; }
            if (RND == 0) {
                *(float2*)((float*)C + (size_t)r0 * D_ + col) = make_float2(o0, o1);
                *(float2*)((float*)C + (size_t)r1 * D_ + col) = make_float2(o2, o3);
            } else {
                if (RND == 2) { o0 *= SCL; o1 *= SCL; o2 *= SCL; o3 *= SCL; }
                *(__half2*)((__half*)C + (size_t)r0 * D_ + col) = __floats2half2_rn(o0, o1);
                *(__half2*)((__half*)C + (size_t)r1 * D_ + col) = __floats2half2_rn(o2, o3);
            }
        }
    }
}

// ---------------------------------------------------------------------------
// ns GEMV body (fp32 exact)
// ---------------------------------------------------------------------------
__device__ __forceinline__
void ns_body(float* sm, int ns_idx, const float* __restrict__ x,
             const float* __restrict__ wk_nw, const float* __restrict__ wv_nw,
             const float* __restrict__ wq_nw, float* __restrict__ part) {
    const int p = ns_idx >> 7;
    const int rem = ns_idx & 127;
    const int n = rem >> 1;
    const int kp = rem & 1;
    const int tid = threadIdx.x;
    const int half = tid >> 7, t = tid & 127;
    const int kz = kp * 2 + half;

    float* xs = sm + half * (B_ * 128);
#pragma unroll
    for (int it = 0; it < 2; ++it) {
        int idx = t + it * 128;
        int b = idx >> 5, k4 = (idx & 31) << 2;
        *(float4*)&xs[b * 128 + k4] =
            *(const float4*)(x + (size_t)(b * L_TOT + L_S_ + n) * D_ + kz * 128 + k4);
    }
    __syncthreads();

    const float* nw = (p == 0) ? wk_nw : (p == 1) ? wv_nw : wq_nw;
    const int col4 = t * 4;
    float4 acc[B_];
#pragma unroll
    for (int b = 0; b < B_; ++b) acc[b] = make_float4(0.f, 0.f, 0.f, 0.f);

    const float* wp = nw + (size_t)n * D_ * D_ + (size_t)(kz * 128) * D_ + col4;
#pragma unroll 8
    for (int k = 0; k < 128; ++k) {
        float4 w = *(const float4*)(wp + (size_t)k * D_);
#pragma unroll
        for (int b = 0; b < B_; ++b) {
            float xv = xs[b * 128 + k];
            acc[b].x += xv * w.x; acc[b].y += xv * w.y;
            acc[b].z += xv * w.z; acc[b].w += xv * w.w;
        }
    }
    float* pr = part + (size_t)p * PARTSZ;
#pragma unroll
    for (int b = 0; b < B_; ++b)
        *(float4*)&pr[(size_t)(((kz * 64 + n) * B_) + b) * D_ + col4] = acc[b];
}

// ---------------------------------------------------------------------------
// Mega projection kernel: 1536 blocks, 1:3 interleave of ns : mma blocks.
// ---------------------------------------------------------------------------
__global__ __launch_bounds__(256, 2)
void mega_proj(const __half* __restrict__ Xh, const float* __restrict__ x,
               const __half* __restrict__ Wh,
               const float* __restrict__ wk_sb, const float* __restrict__ wv_sb,
               const float* __restrict__ wq_sb,
               const float* __restrict__ wk_nw, const float* __restrict__ wv_nw,
               const float* __restrict__ wq_nw,
               const int* __restrict__ pad,
               __half* __restrict__ Kp, __half* __restrict__ Vp,
               __half* __restrict__ Qp, float* __restrict__ part) {
    extern __shared__ char smc[];
    const int bid = blockIdx.x;
    const int group = bid >> 2, r = bid & 3;

    if (r == 0) {
        ns_body((float*)smc, group, x, wk_nw, wv_nw, wq_nw, part);
        return;
    }
    const int mi = group * 3 + (r - 1);
    if (mi < 512) {
        proj_body<0, 1, 0>(smc, (mi & 127) * 128, (mi >> 7) * 128, Xh, Wh, wk_sb, Kp, pad);
    } else if (mi < 1024) {
        int i = mi - 512;
        proj_body<0, 1, 1>(smc, (i & 127) * 128, (i >> 7) * 128, Xh, Wh + WSZ, wv_sb, Vp, pad);
    } else {
        int i = mi - 1024;
        proj_body<1, 2, 0>(smc, (i & 31) * 128, (i >> 5) * 128, Xh, Wh + 2 * WSZ, wq_sb, Qp, pad);
    }
}

__global__ __launch_bounds__(256, 2)
void proj_out(const __half* __restrict__ A, const __half* __restrict__ W,
              const float* __restrict__ bias, float* __restrict__ C) {
    extern __shared__ char smc[];
    proj_body<2, 0, 0>(smc, blockIdx.x * 128, blockIdx.y * 128, A, W, bias, C, nullptr);
}

// ---------------------------------------------------------------------------
// Fused ns reduce
// ---------------------------------------------------------------------------
__global__ __launch_bounds__(512)
void ns_reduce_all(const float* __restrict__ part,
                   const float* __restrict__ nbk, const float* __restrict__ nbv,
                   const float* __restrict__ nbq,
                   __half* __restrict__ Kp, __half* __restrict__ Vp,
                   __half* __restrict__ Qp) {
    const int n = blockIdx.x, p = blockIdx.y;
    const int col = threadIdx.x;
    const float* nb = (p == 0) ? nbk : (p == 1) ? nbv : nbq;
    __half* out = (p == 0) ? Kp : (p == 1) ? Vp : Qp;
    const float* pr = part + (size_t)p * PARTSZ;
    const float bias = nb[n * D_ + col];
    const bool qm = (p == 2);
#pragma unroll
    for (int b = 0; b < B_; ++b) {
        float s = bias;
#pragma unroll
        for (int kz = 0; kz < 4; ++kz)
            s += pr[(size_t)(((kz * 64 + n) * B_) + b) * D_ + col];
        if (qm) s *= SCL;
        int orow = qm ? (b * LQPAD + LS_OUT + n) : (b * L_TOT + L_S_ + n);
        out[(size_t)orow * D_ + col] = __float2half_rn(s);
    }
}

// ---------------------------------------------------------------------------
// Flash attention: fp16 mma, no-max softmax, pad via V-zero + mask-col l MMA.
// Per-16-key-chunk fusion (S -> exp -> PV) to cut live registers; 3 CTAs/SM.
// ---------------------------------------------------------------------------
#define KSB 9216                         // 64*72*2 bytes per stage
#define ATT_QB (128 * 72 * 2)
#define PDH_OFF (ATT_QB + 4 * KSB)
#define ATT_SMEM (PDH_OFF + 2 * 128)

__global__ __launch_bounds__(256, 3)
void attn_mma(const __half* __restrict__ Qg, const __half* __restrict__ Kg,
              const __half* __restrict__ Vg, const __half* __restrict__ padh,
              __half* __restrict__ Og) {
    extern __shared__ char smc[];
    __half* Qs = (__half*)smc;
    const uint32_t base = smem_u32(smc);
    const uint32_t ks_u = base + ATT_QB;
    const uint32_t vs_u = base + ATT_QB + 2 * KSB;
    const uint32_t pd_u = base + PDH_OFF;

    const int l = blockIdx.x;
    const int s_ = (l < 148) ? l : ((l < 296) ? (443 - l) : l);
    const int qt = 4 - (s_ >> 6);
    const int rem = s_ & 63;
    const int h = rem >> 3, b = rem & 7;

    const int tid = threadIdx.x, lane = tid & 31, w = tid >> 5;
    const int g = lane >> 2, t4 = lane & 3;
    const int lt = lane >> 3, lr8 = lane & 7;
    const int qbase = qt * 128;
    const int nkt = min(2 * qt + 26, 33);
    const int rl0 = 16 * w + g, rl1 = rl0 + 8;

    auto issue = [&](int kt, int s) {
        if (kt >= nkt) return;
        const int kb = kt * 64;
        const __half* Kb = Kg + (size_t)(b * L_TOT + kb) * D_ + h * HD_;
        const __half* Vb = Vg + (size_t)(b * L_TOT + kb) * D_ + h * HD_;
#pragma unroll
        for (int p = 0; p < 2; ++p) {
            int idx = tid + p * 256;
            int j = idx >> 3, c8 = (idx & 7) * 8;
            cp16(ks_u + (uint32_t)(s * KSB) + (uint32_t)(j * 72 + c8) * 2, Kb + (size_t)j * D_ + c8);
            cp16(vs_u + (uint32_t)(s * KSB) + (uint32_t)(j * 72 + c8) * 2, Vb + (size_t)j * D_ + c8);
        }
        if (kt < 32 && tid < 8)
            cp16(pd_u + (uint32_t)(s * 128 + tid * 16), padh + b * L_S_ + kb + tid * 8);
    };

    issue(0, 0); CP_COMMIT();

#pragma unroll
    for (int p = 0; p < 4; ++p) {
        int idx = tid + p * 256;
        int row = idx >> 3, c8 = (idx & 7) * 8;
        *(uint4*)&Qs[row * 72 + c8] =
            *(const uint4*)(Qg + (size_t)(b * LQPAD + qbase + row) * D_ + h * HD_ + c8);
    }
    __syncthreads();

    uint32_t qa[4][4];
#pragma unroll
    for (int kc = 0; kc < 4; ++kc) {
        qa[kc][0] = *(const uint32_t*)&Qs[rl0 * 72 + kc * 16 + 2 * t4];
        qa[kc][1] = *(const uint32_t*)&Qs[rl1 * 72 + kc * 16 + 2 * t4];
        qa[kc][2] = *(const uint32_t*)&Qs[rl0 * 72 + kc * 16 + 2 * t4 + 8];
        qa[kc][3] = *(const uint32_t*)&Qs[rl1 * 72 + kc * 16 + 2 * t4 + 8];
    }

    float4 oacc[8];
#pragma unroll
    for (int i = 0; i < 8; ++i) oacc[i] = make_float4(0.f, 0.f, 0.f, 0.f);
    float4 lacc = make_float4(0.f, 0.f, 0.f, 0.f);

#pragma unroll 1
    for (int kt = 0; kt < nkt; ++kt) {
        const int s = kt & 1;
        __syncthreads();              // all threads done reading buffer s^1
        issue(kt + 1, s ^ 1);
        CP_COMMIT();
        CP_WAIT1();                   // buffer s (tile kt) complete

        const uint32_t ksb = ks_u + (uint32_t)(s * KSB);
        const uint32_t vsb = vs_u + (uint32_t)(s * KSB);
        const __half* ph = (const __half*)(smc + PDH_OFF + s * 128);

        const int moff = kt * 64 - qbase - 1536;
        const bool docausal = (moff > -64);
        const bool dopad = (kt < 32);

        // Per-16-key chunk: S -> mask -> exp2 -> l-MMA + PV-MMA
#pragma unroll
        for (int jc = 0; jc < 4; ++jc) {
            float4 s0 = make_float4(0.f, 0.f, 0.f, 0.f);
            float4 s1 = make_float4(0.f, 0.f, 0.f, 0.f);
#pragma unroll
            for (int kc = 0; kc < 4; ++kc) {
                uint32_t b0, b1, b2, b3;
                uint32_t addr = ksb +
                    (uint32_t)(((jc * 16 + (lt >> 1) * 8 + lr8) * 72) + kc * 16 + (lt & 1) * 8) * 2;
                ldsm4(b0, b1, b2, b3, addr);
                mma16(s0, qa[kc], b0, b1);
                mma16(s1, qa[kc], b2, b3);
            }

            if (docausal) {
                int j0 = jc * 16 + 2 * t4, j1 = j0 + 1;
                if (j0 + moff > rl0) s0.x = -1e30f;
                if (j1 + moff > rl0) s0.y = -1e30f;
                if (j0 + moff > rl1) s0.z = -1e30f;
                if (j1 + moff > rl1) s0.w = -1e30f;
                if (j0 + 8 + moff > rl0) s1.x = -1e30f;
                if (j1 + 8 + moff > rl0) s1.y = -1e30f;
                if (j0 + 8 + moff > rl1) s1.z = -1e30f;
                if (j1 + 8 + moff > rl1) s1.w = -1e30f;
            }

            uint32_t pa[4];
            pa[0] = h2exp2(packh2(s0.x, s0.y));
            pa[1] = h2exp2(packh2(s0.z, s0.w));
            pa[2] = h2exp2(packh2(s1.x, s1.y));
            pa[3] = h2exp2(packh2(s1.z, s1.w));

            uint32_t m0c = 0, m1c = 0;
            if (lane < 4) {
                if (dopad) {
                    m0c = *(const uint32_t*)&ph[jc * 16 + 2 * lane];
                    m1c = *(const uint32_t*)&ph[jc * 16 + 2 * lane + 8];
                } else {
                    m0c = 0x3C003C00u; m1c = 0x3C003C00u;
                }
            }
            mma16(lacc, pa, m0c, m1c);
#pragma unroll
            for (int dtp = 0; dtp < 4; ++dtp) {
                uint32_t v0, v1, v2, v3;
                uint32_t addr = vsb +
                    (uint32_t)(((jc * 16 + (lt & 1) * 8 + lr8) * 72) + (dtp * 2 + (lt >> 1)) * 8) * 2;
                ldsm4t(v0, v1, v2, v3, addr);
                mma16(oacc[2 * dtp], pa, v0, v1);
                mma16(oacc[2 * dtp + 1], pa, v2, v3);
            }
        }
    }

    float l0 = __shfl_sync(0xffffffffu, lacc.x, lane & 28);
    float l1 = __shfl_sync(0xffffffffu, lacc.z, lane & 28);

    float il0 = 1.f / l0, il1 = 1.f / l1;
#pragma unroll
    for (int dt = 0; dt < 8; ++dt) {
        int col = h * HD_ + dt * 8 + 2 * t4;
        size_t r0 = (size_t)(b * LQPAD + qbase + rl0) * D_ + col;
        size_t r1 = (size_t)(b * LQPAD + qbase + rl1) * D_ + col;
        *(__half2*)(Og + r0) = __floats2half2_rn(oacc[dt].x * il0, oacc[dt].y * il0);
        *(__half2*)(Og + r1) = __floats2half2_rn(oacc[dt].z * il1, oacc[dt].w * il1);
    }
}

// ---------------------------------------------------------------------------
extern "C" void kernel_launch(void* const* d_in, const int* in_sizes, int n_in,
                              void* d_out, int out_size) {
    const float* x     = (const float*)d_in[0];
    const int*   pad   = (const int*)d_in[1];
    const float* wq_sw = (const float*)d_in[4];
    const float* wq_sb = (const float*)d_in[5];
    const float* wq_nw = (const float*)d_in[6];
    const float* wq_nb = (const float*)d_in[7];
    const float* wk_sw = (const float*)d_in[8];
    const float* wk_sb = (const float*)d_in[9];
    const float* wk_nw = (const float*)d_in[10];
    const float* wk_nb = (const float*)d_in[11];
    const float* wv_sw = (const float*)d_in[12];
    const float* wv_sb = (const float*)d_in[13];
    const float* wv_nw = (const float*)d_in[14];
    const float* wv_nb = (const float*)d_in[15];
    const float* out_w = (const float*)d_in[16];
    const float* out_b = (const float*)d_in[17];
    float* out = (float*)d_out;

    __half *Kp, *Vp, *Qp, *Ap, *Xh, *Wh, *Ph;
    float *Pp;
    cudaGetSymbolAddress((void**)&Kp, g_K);
    cudaGetSymbolAddress((void**)&Vp, g_V);
    cudaGetSymbolAddress((void**)&Qp, g_Q);
    cudaGetSymbolAddress((void**)&Ap, g_A);
    cudaGetSymbolAddress((void**)&Pp, g_Part);
    cudaGetSymbolAddress((void**)&Xh, g_Xh);
    cudaGetSymbolAddress((void**)&Wh, g_Wh);
    cudaGetSymbolAddress((void**)&Ph, g_PadH);

    cudaFuncSetAttribute((const void*)mega_proj, cudaFuncAttributeMaxDynamicSharedMemorySize, PJ_SMEM);
    cudaFuncSetAttribute((const void*)proj_out, cudaFuncAttributeMaxDynamicSharedMemorySize, PJ_SMEM);
    cudaFuncSetAttribute((const void*)attn_mma, cudaFuncAttributeMaxDynamicSharedMemorySize, ATT_SMEM);

    prep_all<<<8448 + 1024 + 8, 256>>>(x, wk_sw, wv_sw, wq_sw, out_w, pad, Xh, Wh, Ph);

    mega_proj<<<1536, 256, PJ_SMEM>>>(Xh, x, Wh, wk_sb, wv_sb, wq_sb,
                                      wk_nw, wv_nw, wq_nw, pad, Kp, Vp, Qp, Pp);
    ns_reduce_all<<<dim3(64, 3), 512>>>(Pp, wk_nb, wv_nb, wq_nb, Kp, Vp, Qp);

    attn_mma<<<320, 256, ATT_SMEM>>>(Qp, Kp, Vp, Ph, Ap);

    proj_out<<<dim3(36, 4), 256, PJ_SMEM>>>(Ap, Wh + 3 * WSZ, out_b, out);
}

// round 14
// speedup vs baseline: 1.0532x; 1.0532x over previous
#include <cuda_runtime.h>
#include <cuda_fp16.h>
#include <cstdint>

// Problem constants
#define B_      8
#define D_      512
#define H_      8
#define HD_     64
#define L_NS_   64
#define L_S_    2048
#define L_TOT   2112
#define LS_OUT  512
#define LQ_     576
#define LQPAD   640

// Q scale: 1/sqrt(64) * log2(e)  (exp2 domain)
#define SCL 0.18033688011112042f

// Scratch (allocation-free device globals)
__device__ __half g_K[B_ * L_TOT * D_];
__device__ __half g_V[B_ * L_TOT * D_];
__device__ __half g_Q[B_ * LQPAD * D_];          // rows 576-639 stay zero
__device__ __half g_A[B_ * LQPAD * D_];          // attention out (fp16)
__device__ float  g_Part[3 * 4 * 64 * B_ * D_];
__device__ __half g_Xh[B_ * L_TOT * D_];         // fp16 x
__device__ __half g_Wh[4 * D_ * D_];             // fp16 wk_sw, wv_sw, wq_sw, out_w
__device__ __half g_PadH[B_ * L_S_];             // fp16 0/1 pad mask

#define WSZ ((size_t)D_ * D_)
#define PARTSZ ((size_t)4 * 64 * B_ * D_)

// ---------------------------------------------------------------------------
// Helpers
// ---------------------------------------------------------------------------
__device__ __forceinline__ uint32_t smem_u32(const void* p) {
    uint32_t a;
    asm("{ .reg .u64 t; cvta.to.shared.u64 t, %1; cvt.u32.u64 %0, t; }" : "=r"(a) : "l"(p));
    return a;
}
__device__ __forceinline__ uint32_t packh2(float a, float b) {
    __half2 h = __floats2half2_rn(a, b);
    return *(uint32_t*)&h;
}
__device__ __forceinline__ uint32_t h2exp2(uint32_t h) {
    uint32_t r; asm("ex2.approx.f16x2 %0, %1;" : "=r"(r) : "r"(h)); return r;
}
__device__ __forceinline__ void mma16(float4& d, const uint32_t a[4], uint32_t b0, uint32_t b1) {
    asm volatile(
        "mma.sync.aligned.m16n8k16.row.col.f32.f16.f16.f32 "
        "{%0,%1,%2,%3}, {%4,%5,%6,%7}, {%8,%9}, {%0,%1,%2,%3};"
        : "+f"(d.x), "+f"(d.y), "+f"(d.z), "+f"(d.w)
        : "r"(a[0]), "r"(a[1]), "r"(a[2]), "r"(a[3]), "r"(b0), "r"(b1));
}
__device__ __forceinline__ void ldsm4(uint32_t& r0, uint32_t& r1, uint32_t& r2, uint32_t& r3,
                                      uint32_t addr) {
    asm volatile("ldmatrix.sync.aligned.m8n8.x4.shared.b16 {%0,%1,%2,%3}, [%4];"
                 : "=r"(r0), "=r"(r1), "=r"(r2), "=r"(r3) : "r"(addr));
}
__device__ __forceinline__ void ldsm4t(uint32_t& r0, uint32_t& r1, uint32_t& r2, uint32_t& r3,
                                       uint32_t addr) {
    asm volatile("ldmatrix.sync.aligned.m8n8.x4.trans.shared.b16 {%0,%1,%2,%3}, [%4];"
                 : "=r"(r0), "=r"(r1), "=r"(r2), "=r"(r3) : "r"(addr));
}
__device__ __forceinline__ void cp16(uint32_t dst, const void* src) {
    asm volatile("cp.async.cg.shared.global [%0], [%1], 16;" :: "r"(dst), "l"(src));
}
#define CP_COMMIT() asm volatile("cp.async.commit_group;" ::: "memory")
#define CP_WAIT1()  asm volatile("cp.async.wait_group 1;" ::: "memory")
#define CP_WAIT2()  asm volatile("cp.async.wait_group 2;" ::: "memory")

// ---------------------------------------------------------------------------
// Fused prep: x->fp16, 4 weights->fp16, pad->fp16
// ---------------------------------------------------------------------------
#define XN4L ((long)B_ * L_TOT * D_ / 4)

__global__ __launch_bounds__(256)
void prep_all(const float* __restrict__ x,
              const float* __restrict__ w0, const float* __restrict__ w1,
              const float* __restrict__ w2, const float* __restrict__ w3,
              const int* __restrict__ pad,
              __half* __restrict__ Xh, __half* __restrict__ Wh,
              __half* __restrict__ PadH) {
    long i = (long)blockIdx.x * 256 + threadIdx.x;
    if (i < XN4L) {
        float4 v = ((const float4*)x)[i];
        ((__half2*)Xh)[2 * i] = __floats2half2_rn(v.x, v.y);
        ((__half2*)Xh)[2 * i + 1] = __floats2half2_rn(v.z, v.w);
        return;
    }
    long j = i - XN4L;
    if (j < 262144) {
        int which = (int)(j >> 16);
        long off = j & 65535;
        const float* w = (which == 0) ? w0 : (which == 1) ? w1 : (which == 2) ? w2 : w3;
        float4 v = ((const float4*)w)[off];
        __half2* dst = (__half2*)(Wh + (size_t)which * WSZ);
        dst[2 * off] = __floats2half2_rn(v.x, v.y);
        dst[2 * off + 1] = __floats2half2_rn(v.z, v.w);
        return;
    }
    long k = j - 262144;
    if (k < (long)(B_ * L_S_ / 8)) {
        long base = k * 8;
#pragma unroll
        for (int q = 0; q < 8; ++q)
            PadH[base + q] = __int2half_rn(pad[base + q] ? 1 : 0);
    }
}

// ---------------------------------------------------------------------------
// Dense projection body, fp16 mma m16n8k16 + ldmatrix, 3-stage cp.async.
// ---------------------------------------------------------------------------
template <int MODE> __device__ __forceinline__ int arow_of(int mi) {
    if (MODE == 0) return (mi >> 11) * L_TOT + (mi & 2047);
    if (MODE == 1) return (mi >> 9) * L_TOT + 1536 + (mi & 511);
    return ((unsigned)mi / 576) * LQPAD + ((unsigned)mi % 576);
}
template <int MODE> __device__ __forceinline__ int crow_of(int mi) {
    if (MODE == 0) return (mi >> 11) * L_TOT + (mi & 2047);
    if (MODE == 1) return (mi >> 9) * LQPAD + (mi & 511);
    return mi;
}

#define PH_AS (128 * 40)
#define PH_WS (32 * 136)
#define PJ_SMEM (3 * (PH_AS + PH_WS) * 2)

template <int MODE, int RND, int PADV>
__device__ __forceinline__
void proj_body(char* smc, int m0, int n0,
               const __half* __restrict__ A, const __half* __restrict__ W,
               const float* __restrict__ bias, void* __restrict__ C,
               const int* __restrict__ pad) {
    const uint32_t as_u = smem_u32(smc);
    const uint32_t ws_u = as_u + 3 * PH_AS * 2;

    const int tid = threadIdx.x, lane = tid & 31;
    const int warp = tid >> 5, wm = warp >> 2, wn = warp & 3;
    const int g = lane >> 2, t4 = lane & 3;
    const int lt = lane >> 3, lr8 = lane & 7;

    const int ar = tid >> 2, aseg = (tid & 3) * 8;
    const __half* pA0 = A + (size_t)arow_of<MODE>(m0 + ar) * D_ + aseg;
    const __half* pA1 = A + (size_t)arow_of<MODE>(m0 + 64 + ar) * D_ + aseg;
    const int wr = tid >> 4, wseg = (tid & 15) * 8;
    const __half* pW = W + n0 + wseg;

    auto issue = [&](int c, int s) {
        const int k0 = c * 32;
        uint32_t ad = as_u + (uint32_t)(s * PH_AS) * 2;
        cp16(ad + (uint32_t)(ar * 40 + aseg) * 2, pA0 + k0);
        cp16(ad + (uint32_t)((ar + 64) * 40 + aseg) * 2, pA1 + k0);
        uint32_t wd = ws_u + (uint32_t)(s * PH_WS) * 2;
        cp16(wd + (uint32_t)(wr * 136 + wseg) * 2, pW + (size_t)(k0 + wr) * D_);
        cp16(wd + (uint32_t)((wr + 16) * 136 + wseg) * 2, pW + (size_t)(k0 + wr + 16) * D_);
    };

    float4 acc[4][4];
#pragma unroll
    for (int i = 0; i < 4; ++i)
#pragma unroll
        for (int j = 0; j < 4; ++j) acc[i][j] = make_float4(0.f, 0.f, 0.f, 0.f);

    issue(0, 0); CP_COMMIT();
    issue(1, 1); CP_COMMIT();

#pragma unroll 1
    for (int c = 0; c < 16; ++c) {
        const int s = c % 3;
        CP_WAIT1();
        __syncthreads();
        if (c + 2 < 16) issue(c + 2, (c + 2) % 3);
        CP_COMMIT();

        const uint32_t as_ = as_u + (uint32_t)(s * PH_AS) * 2;
        const uint32_t ws_ = ws_u + (uint32_t)(s * PH_WS) * 2;
#pragma unroll
        for (int kc = 0; kc < 2; ++kc) {
            uint32_t af[4][4], bf[4][2];
#pragma unroll
            for (int mi = 0; mi < 4; ++mi) {
                uint32_t addr = as_ +
                    (uint32_t)(((wm * 64 + mi * 16 + (lane & 15)) * 40) + kc * 16 + (lane >> 4) * 8) * 2;
                ldsm4(af[mi][0], af[mi][1], af[mi][2], af[mi][3], addr);
            }
#pragma unroll
            for (int pr = 0; pr < 2; ++pr) {
                uint32_t addr = ws_ +
                    (uint32_t)(((kc * 16 + (lt & 1) * 8 + lr8) * 136) + wn * 32 + (pr * 2 + (lt >> 1)) * 8) * 2;
                ldsm4t(bf[2 * pr][0], bf[2 * pr][1], bf[2 * pr + 1][0], bf[2 * pr + 1][1], addr);
            }
#pragma unroll
            for (int mi = 0; mi < 4; ++mi)
#pragma unroll
                for (int ni = 0; ni < 4; ++ni)
                    mma16(acc[mi][ni], af[mi], bf[ni][0], bf[ni][1]);
        }
    }

    float pm[4][2];
    if (PADV) {
#pragma unroll
        for (int mi = 0; mi < 4; ++mi) {
            int mr0 = m0 + wm * 64 + mi * 16 + g;
            int mr1 = mr0 + 8;
            pm[mi][0] = pad[(mr0 >> 11) * L_S_ + (mr0 & 2047)] ? 1.f : 0.f;
            pm[mi][1] = pad[(mr1 >> 11) * L_S_ + (mr1 & 2047)] ? 1.f : 0.f;
        }
    }

#pragma unroll
    for (int ni = 0; ni < 4; ++ni) {
        int col = n0 + wn * 32 + ni * 8 + 2 * t4;
        float2 bv = *(const float2*)(bias + col);
#pragma unroll
        for (int mi = 0; mi < 4; ++mi) {
            int r0 = crow_of<MODE>(m0 + wm * 64 + mi * 16 + g);
            int r1 = crow_of<MODE>(m0 + wm * 64 + mi * 16 + g + 8);
            float o0 = acc[mi][ni].x + bv.x, o1 = acc[mi][ni].y + bv.y;
            float o2 = acc[mi][ni].z + bv.x, o3 = acc[mi][ni].w + bv.y;
            if (PADV) { o0 *= pm[mi][0]; o1 *= pm[mi][0]; o2 *= pm[mi][1]; o3 *= pm[mi][1]; }
            if (RND == 0) {
                *(float2*)((float*)C + (size_t)r0 * D_ + col) = make_float2(o0, o1);
                *(float2*)((float*)C + (size_t)r1 * D_ + col) = make_float2(o2, o3);
            } else {
                if (RND == 2) { o0 *= SCL; o1 *= SCL; o2 *= SCL; o3 *= SCL; }
                *(__half2*)((__half*)C + (size_t)r0 * D_ + col) = __floats2half2_rn(o0, o1);
                *(__half2*)((__half*)C + (size_t)r1 * D_ + col) = __floats2half2_rn(o2, o3);
            }
        }
    }
}

// ---------------------------------------------------------------------------
// ns GEMV body (fp32 exact)
// ---------------------------------------------------------------------------
__device__ __forceinline__
void ns_body(float* sm, int ns_idx, const float* __restrict__ x,
             const float* __restrict__ wk_nw, const float* __restrict__ wv_nw,
             const float* __restrict__ wq_nw, float* __restrict__ part) {
    const int p = ns_idx >> 7;
    const int rem = ns_idx & 127;
    const int n = rem >> 1;
    const int kp = rem & 1;
    const int tid = threadIdx.x;
    const int half = tid >> 7, t = tid & 127;
    const int kz = kp * 2 + half;

    float* xs = sm + half * (B_ * 128);
#pragma unroll
    for (int it = 0; it < 2; ++it) {
        int idx = t + it * 128;
        int b = idx >> 5, k4 = (idx & 31) << 2;
        *(float4*)&xs[b * 128 + k4] =
            *(const float4*)(x + (size_t)(b * L_TOT + L_S_ + n) * D_ + kz * 128 + k4);
    }
    __syncthreads();

    const float* nw = (p == 0) ? wk_nw : (p == 1) ? wv_nw : wq_nw;
    const int col4 = t * 4;
    float4 acc[B_];
#pragma unroll
    for (int b = 0; b < B_; ++b) acc[b] = make_float4(0.f, 0.f, 0.f, 0.f);

    const float* wp = nw + (size_t)n * D_ * D_ + (size_t)(kz * 128) * D_ + col4;
#pragma unroll 8
    for (int k = 0; k < 128; ++k) {
        float4 w = *(const float4*)(wp + (size_t)k * D_);
#pragma unroll
        for (int b = 0; b < B_; ++b) {
            float xv = xs[b * 128 + k];
            acc[b].x += xv * w.x; acc[b].y += xv * w.y;
            acc[b].z += xv * w.z; acc[b].w += xv * w.w;
        }
    }
    float* pr = part + (size_t)p * PARTSZ;
#pragma unroll
    for (int b = 0; b < B_; ++b)
        *(float4*)&pr[(size_t)(((kz * 64 + n) * B_) + b) * D_ + col4] = acc[b];
}

// ---------------------------------------------------------------------------
// Mega projection kernel: 1536 blocks, 1:3 interleave of ns : mma blocks.
// ---------------------------------------------------------------------------
__global__ __launch_bounds__(256, 2)
void mega_proj(const __half* __restrict__ Xh, const float* __restrict__ x,
               const __half* __restrict__ Wh,
               const float* __restrict__ wk_sb, const float* __restrict__ wv_sb,
               const float* __restrict__ wq_sb,
               const float* __restrict__ wk_nw, const float* __restrict__ wv_nw,
               const float* __restrict__ wq_nw,
               const int* __restrict__ pad,
               __half* __restrict__ Kp, __half* __restrict__ Vp,
               __half* __restrict__ Qp, float* __restrict__ part) {
    extern __shared__ char smc[];
    const int bid = blockIdx.x;
    const int group = bid >> 2, r = bid & 3;

    if (r == 0) {
        ns_body((float*)smc, group, x, wk_nw, wv_nw, wq_nw, part);
        return;
    }
    const int mi = group * 3 + (r - 1);
    if (mi < 512) {
        proj_body<0, 1, 0>(smc, (mi & 127) * 128, (mi >> 7) * 128, Xh, Wh, wk_sb, Kp, pad);
    } else if (mi < 1024) {
        int i = mi - 512;
        proj_body<0, 1, 1>(smc, (i & 127) * 128, (i >> 7) * 128, Xh, Wh + WSZ, wv_sb, Vp, pad);
    } else {
        int i = mi - 1024;
        proj_body<1, 2, 0>(smc, (i & 31) * 128, (i >> 5) * 128, Xh, Wh + 2 * WSZ, wq_sb, Qp, pad);
    }
}

__global__ __launch_bounds__(256, 2)
void proj_out(const __half* __restrict__ A, const __half* __restrict__ W,
              const float* __restrict__ bias, float* __restrict__ C) {
    extern __shared__ char smc[];
    proj_body<2, 0, 0>(smc, blockIdx.x * 128, blockIdx.y * 128, A, W, bias, C, nullptr);
}

// ---------------------------------------------------------------------------
// Fused ns reduce
// ---------------------------------------------------------------------------
__global__ __launch_bounds__(512)
void ns_reduce_all(const float* __restrict__ part,
                   const float* __restrict__ nbk, const float* __restrict__ nbv,
                   const float* __restrict__ nbq,
                   __half* __restrict__ Kp, __half* __restrict__ Vp,
                   __half* __restrict__ Qp) {
    const int n = blockIdx.x, p = blockIdx.y;
    const int col = threadIdx.x;
    const float* nb = (p == 0) ? nbk : (p == 1) ? nbv : nbq;
    __half* out = (p == 0) ? Kp : (p == 1) ? Vp : Qp;
    const float* pr = part + (size_t)p * PARTSZ;
    const float bias = nb[n * D_ + col];
    const bool qm = (p == 2);
#pragma unroll
    for (int b = 0; b < B_; ++b) {
        float s = bias;
#pragma unroll
        for (int kz = 0; kz < 4; ++kz)
            s += pr[(size_t)(((kz * 64 + n) * B_) + b) * D_ + col];
        if (qm) s *= SCL;
        int orow = qm ? (b * LQPAD + LS_OUT + n) : (b * L_TOT + L_S_ + n);
        out[(size_t)orow * D_ + col] = __float2half_rn(s);
    }
}

// ---------------------------------------------------------------------------
// Flash attention (R11 structure: full-tile S -> exp -> PV), fp16 mma,
// no-max softmax, pad via V-zero + mask-col l MMA; 3-stage cp.async rings
// with wait_group 2 (two tiles in flight).
// ---------------------------------------------------------------------------
#define KSB 9216                         // 64*72*2 bytes per stage
#define ATT_QB (128 * 72 * 2)
#define PDH_OFF (ATT_QB + 6 * KSB)       // 3 stages x 128 B pad
#define ATT_SMEM (PDH_OFF + 3 * 128)

__global__ __launch_bounds__(256, 2)
void attn_mma(const __half* __restrict__ Qg, const __half* __restrict__ Kg,
              const __half* __restrict__ Vg, const __half* __restrict__ padh,
              __half* __restrict__ Og) {
    extern __shared__ char smc[];
    __half* Qs = (__half*)smc;
    const uint32_t base = smem_u32(smc);
    const uint32_t ks_u = base + ATT_QB;
    const uint32_t vs_u = base + ATT_QB + 3 * KSB;
    const uint32_t pd_u = base + PDH_OFF;

    const int l = blockIdx.x;
    const int s_ = (l < 148) ? l : ((l < 296) ? (443 - l) : l);
    const int qt = 4 - (s_ >> 6);
    const int rem = s_ & 63;
    const int h = rem >> 3, b = rem & 7;

    const int tid = threadIdx.x, lane = tid & 31, w = tid >> 5;
    const int g = lane >> 2, t4 = lane & 3;
    const int lt = lane >> 3, lr8 = lane & 7;
    const int qbase = qt * 128;
    const int nkt = min(2 * qt + 26, 33);
    const int rl0 = 16 * w + g, rl1 = rl0 + 8;

    auto issue = [&](int kt, int s) {
        if (kt >= nkt) return;
        const int kb = kt * 64;
        const __half* Kb = Kg + (size_t)(b * L_TOT + kb) * D_ + h * HD_;
        const __half* Vb = Vg + (size_t)(b * L_TOT + kb) * D_ + h * HD_;
#pragma unroll
        for (int p = 0; p < 2; ++p) {
            int idx = tid + p * 256;
            int j = idx >> 3, c8 = (idx & 7) * 8;
            cp16(ks_u + (uint32_t)(s * KSB) + (uint32_t)(j * 72 + c8) * 2, Kb + (size_t)j * D_ + c8);
            cp16(vs_u + (uint32_t)(s * KSB) + (uint32_t)(j * 72 + c8) * 2, Vb + (size_t)j * D_ + c8);
        }
        if (kt < 32 && tid < 8)
            cp16(pd_u + (uint32_t)(s * 128 + tid * 16), padh + b * L_S_ + kb + tid * 8);
    };

    issue(0, 0); CP_COMMIT();
    issue(1, 1); CP_COMMIT();

    // Stage Q (fp16, pre-scaled)
#pragma unroll
    for (int p = 0; p < 4; ++p) {
        int idx = tid + p * 256;
        int row = idx >> 3, c8 = (idx & 7) * 8;
        *(uint4*)&Qs[row * 72 + c8] =
            *(const uint4*)(Qg + (size_t)(b * LQPAD + qbase + row) * D_ + h * HD_ + c8);
    }
    __syncthreads();

    uint32_t qa[4][4];
#pragma unroll
    for (int kc = 0; kc < 4; ++kc) {
        qa[kc][0] = *(const uint32_t*)&Qs[rl0 * 72 + kc * 16 + 2 * t4];
        qa[kc][1] = *(const uint32_t*)&Qs[rl1 * 72 + kc * 16 + 2 * t4];
        qa[kc][2] = *(const uint32_t*)&Qs[rl0 * 72 + kc * 16 + 2 * t4 + 8];
        qa[kc][3] = *(const uint32_t*)&Qs[rl1 * 72 + kc * 16 + 2 * t4 + 8];
    }

    float4 oacc[8];
#pragma unroll
    for (int i = 0; i < 8; ++i) oacc[i] = make_float4(0.f, 0.f, 0.f, 0.f);
    float4 lacc = make_float4(0.f, 0.f, 0.f, 0.f);

#pragma unroll 1
    for (int kt = 0; kt < nkt; ++kt) {
        const int s = kt % 3;
        __syncthreads();              // readers of stage (kt+2)%3 == (kt-1)%3 done
        issue(kt + 2, (kt + 2) % 3);
        CP_COMMIT();
        CP_WAIT2();                   // group kt complete (<=2 outstanding)

        const uint32_t ksb = ks_u + (uint32_t)(s * KSB);
        const uint32_t vsb = vs_u + (uint32_t)(s * KSB);
        const __half* ph = (const __half*)(smc + PDH_OFF + s * 128);

        // S = Q K^T (full tile)
        float4 sacc[8];
#pragma unroll
        for (int nt = 0; nt < 8; ++nt) sacc[nt] = make_float4(0.f, 0.f, 0.f, 0.f);
#pragma unroll
        for (int kc = 0; kc < 4; ++kc) {
#pragma unroll
            for (int ntp = 0; ntp < 4; ++ntp) {
                uint32_t b0, b1, b2, b3;
                uint32_t addr = ksb +
                    (uint32_t)(((ntp * 16 + (lt >> 1) * 8 + lr8) * 72) + kc * 16 + (lt & 1) * 8) * 2;
                ldsm4(b0, b1, b2, b3, addr);
                mma16(sacc[2 * ntp], qa[kc], b0, b1);
                mma16(sacc[2 * ntp + 1], qa[kc], b2, b3);
            }
        }

        // Causal mask (pad handled via V-zero + mask column)
        const int moff = kt * 64 - qbase - 1536;
        if (moff > -64) {
#pragma unroll
            for (int nt = 0; nt < 8; ++nt) {
                int j0 = nt * 8 + 2 * t4, j1 = j0 + 1;
                if (j0 + moff > rl0) sacc[nt].x = -1e30f;
                if (j1 + moff > rl0) sacc[nt].y = -1e30f;
                if (j0 + moff > rl1) sacc[nt].z = -1e30f;
                if (j1 + moff > rl1) sacc[nt].w = -1e30f;
            }
        }

        // P = exp2(S) f16x2; O += P V; l += P @ maskcol
        const bool dopad = (kt < 32);
#pragma unroll
        for (int jc = 0; jc < 4; ++jc) {
            uint32_t pa[4];
            pa[0] = h2exp2(packh2(sacc[2 * jc].x, sacc[2 * jc].y));
            pa[1] = h2exp2(packh2(sacc[2 * jc].z, sacc[2 * jc].w));
            pa[2] = h2exp2(packh2(sacc[2 * jc + 1].x, sacc[2 * jc + 1].y));
            pa[3] = h2exp2(packh2(sacc[2 * jc + 1].z, sacc[2 * jc + 1].w));
            uint32_t m0c = 0, m1c = 0;
            if (lane < 4) {
                if (dopad) {
                    m0c = *(const uint32_t*)&ph[jc * 16 + 2 * lane];
                    m1c = *(const uint32_t*)&ph[jc * 16 + 2 * lane + 8];
                } else {
                    m0c = 0x3C003C00u; m1c = 0x3C003C00u;
                }
            }
            mma16(lacc, pa, m0c, m1c);
#pragma unroll
            for (int dtp = 0; dtp < 4; ++dtp) {
                uint32_t v0, v1, v2, v3;
                uint32_t addr = vsb +
                    (uint32_t)(((jc * 16 + (lt & 1) * 8 + lr8) * 72) + (dtp * 2 + (lt >> 1)) * 8) * 2;
                ldsm4t(v0, v1, v2, v3, addr);
                mma16(oacc[2 * dtp], pa, v0, v1);
                mma16(oacc[2 * dtp + 1], pa, v2, v3);
            }
        }
    }

    float l0 = __shfl_sync(0xffffffffu, lacc.x, lane & 28);
    float l1 = __shfl_sync(0xffffffffu, lacc.z, lane & 28);

    float il0 = 1.f / l0, il1 = 1.f / l1;
#pragma unroll
    for (int dt = 0; dt < 8; ++dt) {
        int col = h * HD_ + dt * 8 + 2 * t4;
        size_t r0 = (size_t)(b * LQPAD + qbase + rl0) * D_ + col;
        size_t r1 = (size_t)(b * LQPAD + qbase + rl1) * D_ + col;
        *(__half2*)(Og + r0) = __floats2half2_rn(oacc[dt].x * il0, oacc[dt].y * il0);
        *(__half2*)(Og + r1) = __floats2half2_rn(oacc[dt].z * il1, oacc[dt].w * il1);
    }
}

// ---------------------------------------------------------------------------
extern "C" void kernel_launch(void* const* d_in, const int* in_sizes, int n_in,
                              void* d_out, int out_size) {
    const float* x     = (const float*)d_in[0];
    const int*   pad   = (const int*)d_in[1];
    const float* wq_sw = (const float*)d_in[4];
    const float* wq_sb = (const float*)d_in[5];
    const float* wq_nw = (const float*)d_in[6];
    const float* wq_nb = (const float*)d_in[7];
    const float* wk_sw = (const float*)d_in[8];
    const float* wk_sb = (const float*)d_in[9];
    const float* wk_nw = (const float*)d_in[10];
    const float* wk_nb = (const float*)d_in[11];
    const float* wv_sw = (const float*)d_in[12];
    const float* wv_sb = (const float*)d_in[13];
    const float* wv_nw = (const float*)d_in[14];
    const float* wv_nb = (const float*)d_in[15];
    const float* out_w = (const float*)d_in[16];
    const float* out_b = (const float*)d_in[17];
    float* out = (float*)d_out;

    __half *Kp, *Vp, *Qp, *Ap, *Xh, *Wh, *Ph;
    float *Pp;
    cudaGetSymbolAddress((void**)&Kp, g_K);
    cudaGetSymbolAddress((void**)&Vp, g_V);
    cudaGetSymbolAddress((void**)&Qp, g_Q);
    cudaGetSymbolAddress((void**)&Ap, g_A);
    cudaGetSymbolAddress((void**)&Pp, g_Part);
    cudaGetSymbolAddress((void**)&Xh, g_Xh);
    cudaGetSymbolAddress((void**)&Wh, g_Wh);
    cudaGetSymbolAddress((void**)&Ph, g_PadH);

    cudaFuncSetAttribute((const void*)mega_proj, cudaFuncAttributeMaxDynamicSharedMemorySize, PJ_SMEM);
    cudaFuncSetAttribute((const void*)proj_out, cudaFuncAttributeMaxDynamicSharedMemorySize, PJ_SMEM);
    cudaFuncSetAttribute((const void*)attn_mma, cudaFuncAttributeMaxDynamicSharedMemorySize, ATT_SMEM);

    prep_all<<<8448 + 1024 + 8, 256>>>(x, wk_sw, wv_sw, wq_sw, out_w, pad, Xh, Wh, Ph);

    mega_proj<<<1536, 256, PJ_SMEM>>>(Xh, x, Wh, wk_sb, wv_sb, wq_sb,
                                      wk_nw, wv_nw, wq_nw, pad, Kp, Vp, Qp, Pp);
    ns_reduce_all<<<dim3(64, 3), 512>>>(Pp, wk_nb, wv_nb, wq_nb, Kp, Vp, Qp);

    attn_mma<<<320, 256, ATT_SMEM>>>(Qp, Kp, Vp, Ph, Ap);

    proj_out<<<dim3(36, 4), 256, PJ_SMEM>>>(Ap, Wh + 3 * WSZ, out_b, out);
}

// round 16
// speedup vs baseline: 1.0551x; 1.0018x over previous
#include <cuda_runtime.h>
#include <cuda_fp16.h>
#include <cstdint>

// Problem constants
#define B_      8
#define D_      512
#define H_      8
#define HD_     64
#define L_NS_   64
#define L_S_    2048
#define L_TOT   2112
#define LS_OUT  512
#define LQ_     576
#define LQPAD   640

// Q scale: 1/sqrt(64) * log2(e)  (exp2 domain)
#define SCL 0.18033688011112042f

// Scratch (allocation-free device globals)
__device__ __half g_K[B_ * L_TOT * D_];
__device__ __half g_V[B_ * L_TOT * D_];
__device__ __half g_Q[B_ * LQPAD * D_];          // rows 576-639 stay zero
__device__ __half g_A[B_ * LQPAD * D_];          // attention out (fp16)
__device__ float  g_Part[3 * 4 * 64 * B_ * D_];
__device__ __half g_Xh[B_ * L_TOT * D_];         // fp16 x
__device__ __half g_Wh[4 * D_ * D_];             // fp16 wk_sw, wv_sw, wq_sw, out_w
__device__ __half g_PadH[B_ * L_S_];             // fp16 0/1 pad mask

#define WSZ ((size_t)D_ * D_)
#define PARTSZ ((size_t)4 * 64 * B_ * D_)

// ---------------------------------------------------------------------------
// Helpers
// ---------------------------------------------------------------------------
__device__ __forceinline__ uint32_t smem_u32(const void* p) {
    uint32_t a;
    asm("{ .reg .u64 t; cvta.to.shared.u64 t, %1; cvt.u32.u64 %0, t; }" : "=r"(a) : "l"(p));
    return a;
}
__device__ __forceinline__ uint32_t packh2(float a, float b) {
    __half2 h = __floats2half2_rn(a, b);
    return *(uint32_t*)&h;
}
__device__ __forceinline__ uint32_t h2exp2(uint32_t h) {
    uint32_t r; asm("ex2.approx.f16x2 %0, %1;" : "=r"(r) : "r"(h)); return r;
}
__device__ __forceinline__ void mma16(float4& d, const uint32_t a[4], uint32_t b0, uint32_t b1) {
    asm volatile(
        "mma.sync.aligned.m16n8k16.row.col.f32.f16.f16.f32 "
        "{%0,%1,%2,%3}, {%4,%5,%6,%7}, {%8,%9}, {%0,%1,%2,%3};"
        : "+f"(d.x), "+f"(d.y), "+f"(d.z), "+f"(d.w)
        : "r"(a[0]), "r"(a[1]), "r"(a[2]), "r"(a[3]), "r"(b0), "r"(b1));
}
__device__ __forceinline__ void ldsm4(uint32_t& r0, uint32_t& r1, uint32_t& r2, uint32_t& r3,
                                      uint32_t addr) {
    asm volatile("ldmatrix.sync.aligned.m8n8.x4.shared.b16 {%0,%1,%2,%3}, [%4];"
                 : "=r"(r0), "=r"(r1), "=r"(r2), "=r"(r3) : "r"(addr));
}
__device__ __forceinline__ void ldsm4t(uint32_t& r0, uint32_t& r1, uint32_t& r2, uint32_t& r3,
                                       uint32_t addr) {
    asm volatile("ldmatrix.sync.aligned.m8n8.x4.trans.shared.b16 {%0,%1,%2,%3}, [%4];"
                 : "=r"(r0), "=r"(r1), "=r"(r2), "=r"(r3) : "r"(addr));
}
__device__ __forceinline__ void cp16(uint32_t dst, const void* src) {
    asm volatile("cp.async.cg.shared.global [%0], [%1], 16;" :: "r"(dst), "l"(src));
}
#define CP_COMMIT() asm volatile("cp.async.commit_group;" ::: "memory")
#define CP_WAIT1()  asm volatile("cp.async.wait_group 1;" ::: "memory")
#define CP_WAIT2()  asm volatile("cp.async.wait_group 2;" ::: "memory")

// ---------------------------------------------------------------------------
// Fused prep: x->fp16, 4 weights->fp16, pad->fp16
// ---------------------------------------------------------------------------
#define XN4L ((long)B_ * L_TOT * D_ / 4)

__global__ __launch_bounds__(256)
void prep_all(const float* __restrict__ x,
              const float* __restrict__ w0, const float* __restrict__ w1,
              const float* __restrict__ w2, const float* __restrict__ w3,
              const int* __restrict__ pad,
              __half* __restrict__ Xh, __half* __restrict__ Wh,
              __half* __restrict__ PadH) {
    long i = (long)blockIdx.x * 256 + threadIdx.x;
    if (i < XN4L) {
        float4 v = ((const float4*)x)[i];
        ((__half2*)Xh)[2 * i] = __floats2half2_rn(v.x, v.y);
        ((__half2*)Xh)[2 * i + 1] = __floats2half2_rn(v.z, v.w);
        return;
    }
    long j = i - XN4L;
    if (j < 262144) {
        int which = (int)(j >> 16);
        long off = j & 65535;
        const float* w = (which == 0) ? w0 : (which == 1) ? w1 : (which == 2) ? w2 : w3;
        float4 v = ((const float4*)w)[off];
        __half2* dst = (__half2*)(Wh + (size_t)which * WSZ);
        dst[2 * off] = __floats2half2_rn(v.x, v.y);
        dst[2 * off + 1] = __floats2half2_rn(v.z, v.w);
        return;
    }
    long k = j - 262144;
    if (k < (long)(B_ * L_S_ / 8)) {
        long base = k * 8;
#pragma unroll
        for (int q = 0; q < 8; ++q)
            PadH[base + q] = __int2half_rn(pad[base + q] ? 1 : 0);
    }
}

// ---------------------------------------------------------------------------
// Dense projection body, fp16 mma m16n8k16 + ldmatrix.
// BK=64, 8 k-iterations, 2-stage cp.async, CANONICAL two-barrier pipeline
// (wait own group, then barrier => all threads' copies visible).
// ---------------------------------------------------------------------------
template <int MODE> __device__ __forceinline__ int arow_of(int mi) {
    if (MODE == 0) return (mi >> 11) * L_TOT + (mi & 2047);
    if (MODE == 1) return (mi >> 9) * L_TOT + 1536 + (mi & 511);
    return ((unsigned)mi / 576) * LQPAD + ((unsigned)mi % 576);
}
template <int MODE> __device__ __forceinline__ int crow_of(int mi) {
    if (MODE == 0) return (mi >> 11) * L_TOT + (mi & 2047);
    if (MODE == 1) return (mi >> 9) * LQPAD + (mi & 511);
    return mi;
}

#define PH_AS (128 * 72)     // halves per A stage (64 data + 8 pad per row)
#define PH_WS (64 * 136)     // halves per W stage (128 data + 8 pad per row)
#define PJ_SMEM (2 * (PH_AS + PH_WS) * 2)

template <int MODE, int RND, int PADV>
__device__ __forceinline__
void proj_body(char* smc, int m0, int n0,
               const __half* __restrict__ A, const __half* __restrict__ W,
               const float* __restrict__ bias, void* __restrict__ C,
               const int* __restrict__ pad) {
    const uint32_t as_u = smem_u32(smc);
    const uint32_t ws_u = as_u + 2 * PH_AS * 2;

    const int tid = threadIdx.x, lane = tid & 31;
    const int warp = tid >> 5, wm = warp >> 2, wn = warp & 3;
    const int g = lane >> 2, t4 = lane & 3;
    const int lt = lane >> 3, lr8 = lane & 7;

    // Loader indices: A 128 rows x 64 halves (4 rows/thread), W 64 rows x 128 halves
    const int ar0 = tid >> 3, aseg = (tid & 7) * 8;
    const __half* pA[4];
#pragma unroll
    for (int p = 0; p < 4; ++p)
        pA[p] = A + (size_t)arow_of<MODE>(m0 + ar0 + p * 32) * D_ + aseg;
    const int wr0 = tid >> 4, wseg = (tid & 15) * 8;
    const __half* pW = W + n0 + wseg;

    auto issue = [&](int c, int s) {
        if (c >= 8) return;
        const int k0 = c * 64;
        uint32_t ad = as_u + (uint32_t)(s * PH_AS) * 2;
#pragma unroll
        for (int p = 0; p < 4; ++p)
            cp16(ad + (uint32_t)((ar0 + p * 32) * 72 + aseg) * 2, pA[p] + k0);
        uint32_t wd = ws_u + (uint32_t)(s * PH_WS) * 2;
#pragma unroll
        for (int p = 0; p < 4; ++p)
            cp16(wd + (uint32_t)((wr0 + p * 16) * 136 + wseg) * 2,
                 pW + (size_t)(k0 + wr0 + p * 16) * D_);
    };

    float4 acc[4][4];
#pragma unroll
    for (int i = 0; i < 4; ++i)
#pragma unroll
        for (int j = 0; j < 4; ++j) acc[i][j] = make_float4(0.f, 0.f, 0.f, 0.f);

    issue(0, 0); CP_COMMIT();

#pragma unroll 1
    for (int c = 0; c < 8; ++c) {
        const int s = c & 1;
        __syncthreads();              // readers of buffer s^1 (iter c-1) done
        issue(c + 1, s ^ 1);
        CP_COMMIT();
        CP_WAIT1();                   // own copies of group c complete
        __syncthreads();              // ALL threads' group-c copies visible

        const uint32_t as_ = as_u + (uint32_t)(s * PH_AS) * 2;
        const uint32_t ws_ = ws_u + (uint32_t)(s * PH_WS) * 2;
#pragma unroll
        for (int kc = 0; kc < 4; ++kc) {
            uint32_t af[4][4], bf[4][2];
#pragma unroll
            for (int mi = 0; mi < 4; ++mi) {
                uint32_t addr = as_ +
                    (uint32_t)(((wm * 64 + mi * 16 + (lane & 15)) * 72) + kc * 16 + (lane >> 4) * 8) * 2;
                ldsm4(af[mi][0], af[mi][1], af[mi][2], af[mi][3], addr);
            }
#pragma unroll
            for (int pr = 0; pr < 2; ++pr) {
                uint32_t addr = ws_ +
                    (uint32_t)(((kc * 16 + (lt & 1) * 8 + lr8) * 136) + wn * 32 + (pr * 2 + (lt >> 1)) * 8) * 2;
                ldsm4t(bf[2 * pr][0], bf[2 * pr][1], bf[2 * pr + 1][0], bf[2 * pr + 1][1], addr);
            }
#pragma unroll
            for (int mi = 0; mi < 4; ++mi)
#pragma unroll
                for (int ni = 0; ni < 4; ++ni)
                    mma16(acc[mi][ni], af[mi], bf[ni][0], bf[ni][1]);
        }
    }

    float pm[4][2];
    if (PADV) {
#pragma unroll
        for (int mi = 0; mi < 4; ++mi) {
            int mr0 = m0 + wm * 64 + mi * 16 + g;
            int mr1 = mr0 + 8;
            pm[mi][0] = pad[(mr0 >> 11) * L_S_ + (mr0 & 2047)] ? 1.f : 0.f;
            pm[mi][1] = pad[(mr1 >> 11) * L_S_ + (mr1 & 2047)] ? 1.f : 0.f;
        }
    }

#pragma unroll
    for (int ni = 0; ni < 4; ++ni) {
        int col = n0 + wn * 32 + ni * 8 + 2 * t4;
        float2 bv = *(const float2*)(bias + col);
#pragma unroll
        for (int mi = 0; mi < 4; ++mi) {
            int r0 = crow_of<MODE>(m0 + wm * 64 + mi * 16 + g);
            int r1 = crow_of<MODE>(m0 + wm * 64 + mi * 16 + g + 8);
            float o0 = acc[mi][ni].x + bv.x, o1 = acc[mi][ni].y + bv.y;
            float o2 = acc[mi][ni].z + bv.x, o3 = acc[mi][ni].w + bv.y;
            if (PADV) { o0 *= pm[mi][0]; o1 *= pm[mi][0]; o2 *= pm[mi][1]; o3 *= pm[mi][1]; }
            if (RND == 0) {
                *(float2*)((float*)C + (size_t)r0 * D_ + col) = make_float2(o0, o1);
                *(float2*)((float*)C + (size_t)r1 * D_ + col) = make_float2(o2, o3);
            } else {
                if (RND == 2) { o0 *= SCL; o1 *= SCL; o2 *= SCL; o3 *= SCL; }
                *(__half2*)((__half*)C + (size_t)r0 * D_ + col) = __floats2half2_rn(o0, o1);
                *(__half2*)((__half*)C + (size_t)r1 * D_ + col) = __floats2half2_rn(o2, o3);
            }
        }
    }
}

// ---------------------------------------------------------------------------
// ns GEMV body (fp32 exact)
// ---------------------------------------------------------------------------
__device__ __forceinline__
void ns_body(float* sm, int ns_idx, const float* __restrict__ x,
             const float* __restrict__ wk_nw, const float* __restrict__ wv_nw,
             const float* __restrict__ wq_nw, float* __restrict__ part) {
    const int p = ns_idx >> 7;
    const int rem = ns_idx & 127;
    const int n = rem >> 1;
    const int kp = rem & 1;
    const int tid = threadIdx.x;
    const int half = tid >> 7, t = tid & 127;
    const int kz = kp * 2 + half;

    float* xs = sm + half * (B_ * 128);
#pragma unroll
    for (int it = 0; it < 2; ++it) {
        int idx = t + it * 128;
        int b = idx >> 5, k4 = (idx & 31) << 2;
        *(float4*)&xs[b * 128 + k4] =
            *(const float4*)(x + (size_t)(b * L_TOT + L_S_ + n) * D_ + kz * 128 + k4);
    }
    __syncthreads();

    const float* nw = (p == 0) ? wk_nw : (p == 1) ? wv_nw : wq_nw;
    const int col4 = t * 4;
    float4 acc[B_];
#pragma unroll
    for (int b = 0; b < B_; ++b) acc[b] = make_float4(0.f, 0.f, 0.f, 0.f);

    const float* wp = nw + (size_t)n * D_ * D_ + (size_t)(kz * 128) * D_ + col4;
#pragma unroll 8
    for (int k = 0; k < 128; ++k) {
        float4 w = *(const float4*)(wp + (size_t)k * D_);
#pragma unroll
        for (int b = 0; b < B_; ++b) {
            float xv = xs[b * 128 + k];
            acc[b].x += xv * w.x; acc[b].y += xv * w.y;
            acc[b].z += xv * w.z; acc[b].w += xv * w.w;
        }
    }
    float* pr = part + (size_t)p * PARTSZ;
#pragma unroll
    for (int b = 0; b < B_; ++b)
        *(float4*)&pr[(size_t)(((kz * 64 + n) * B_) + b) * D_ + col4] = acc[b];
}

// ---------------------------------------------------------------------------
// Mega projection kernel: 1536 blocks, 1:3 interleave of ns : mma blocks.
// ---------------------------------------------------------------------------
__global__ __launch_bounds__(256, 2)
void mega_proj(const __half* __restrict__ Xh, const float* __restrict__ x,
               const __half* __restrict__ Wh,
               const float* __restrict__ wk_sb, const float* __restrict__ wv_sb,
               const float* __restrict__ wq_sb,
               const float* __restrict__ wk_nw, const float* __restrict__ wv_nw,
               const float* __restrict__ wq_nw,
               const int* __restrict__ pad,
               __half* __restrict__ Kp, __half* __restrict__ Vp,
               __half* __restrict__ Qp, float* __restrict__ part) {
    extern __shared__ char smc[];
    const int bid = blockIdx.x;
    const int group = bid >> 2, r = bid & 3;

    if (r == 0) {
        ns_body((float*)smc, group, x, wk_nw, wv_nw, wq_nw, part);
        return;
    }
    const int mi = group * 3 + (r - 1);
    if (mi < 512) {
        proj_body<0, 1, 0>(smc, (mi & 127) * 128, (mi >> 7) * 128, Xh, Wh, wk_sb, Kp, pad);
    } else if (mi < 1024) {
        int i = mi - 512;
        proj_body<0, 1, 1>(smc, (i & 127) * 128, (i >> 7) * 128, Xh, Wh + WSZ, wv_sb, Vp, pad);
    } else {
        int i = mi - 1024;
        proj_body<1, 2, 0>(smc, (i & 31) * 128, (i >> 5) * 128, Xh, Wh + 2 * WSZ, wq_sb, Qp, pad);
    }
}

__global__ __launch_bounds__(256, 2)
void proj_out(const __half* __restrict__ A, const __half* __restrict__ W,
              const float* __restrict__ bias, float* __restrict__ C) {
    extern __shared__ char smc[];
    proj_body<2, 0, 0>(smc, blockIdx.x * 128, blockIdx.y * 128, A, W, bias, C, nullptr);
}

// ---------------------------------------------------------------------------
// Fused ns reduce
// ---------------------------------------------------------------------------
__global__ __launch_bounds__(512)
void ns_reduce_all(const float* __restrict__ part,
                   const float* __restrict__ nbk, const float* __restrict__ nbv,
                   const float* __restrict__ nbq,
                   __half* __restrict__ Kp, __half* __restrict__ Vp,
                   __half* __restrict__ Qp) {
    const int n = blockIdx.x, p = blockIdx.y;
    const int col = threadIdx.x;
    const float* nb = (p == 0) ? nbk : (p == 1) ? nbv : nbq;
    __half* out = (p == 0) ? Kp : (p == 1) ? Vp : Qp;
    const float* pr = part + (size_t)p * PARTSZ;
    const float bias = nb[n * D_ + col];
    const bool qm = (p == 2);
#pragma unroll
    for (int b = 0; b < B_; ++b) {
        float s = bias;
#pragma unroll
        for (int kz = 0; kz < 4; ++kz)
            s += pr[(size_t)(((kz * 64 + n) * B_) + b) * D_ + col];
        if (qm) s *= SCL;
        int orow = qm ? (b * LQPAD + LS_OUT + n) : (b * L_TOT + L_S_ + n);
        out[(size_t)orow * D_ + col] = __float2half_rn(s);
    }
}

// ---------------------------------------------------------------------------
// Flash attention — EXACT R13 version (known good): fp16 mma, no-max softmax,
// pad via V-zero + mask-col l MMA; 3-stage 64-key cp.async rings, wait_group 2.
// ---------------------------------------------------------------------------
#define KSB 9216                         // 64*72*2 bytes per stage
#define ATT_QB (128 * 72 * 2)
#define PDH_OFF (ATT_QB + 6 * KSB)       // 3 stages x 128 B pad
#define ATT_SMEM (PDH_OFF + 3 * 128)

__global__ __launch_bounds__(256, 2)
void attn_mma(const __half* __restrict__ Qg, const __half* __restrict__ Kg,
              const __half* __restrict__ Vg, const __half* __restrict__ padh,
              __half* __restrict__ Og) {
    extern __shared__ char smc[];
    __half* Qs = (__half*)smc;
    const uint32_t base = smem_u32(smc);
    const uint32_t ks_u = base + ATT_QB;
    const uint32_t vs_u = base + ATT_QB + 3 * KSB;
    const uint32_t pd_u = base + PDH_OFF;

    const int l = blockIdx.x;
    const int s_ = (l < 148) ? l : ((l < 296) ? (443 - l) : l);
    const int qt = 4 - (s_ >> 6);
    const int rem = s_ & 63;
    const int h = rem >> 3, b = rem & 7;

    const int tid = threadIdx.x, lane = tid & 31, w = tid >> 5;
    const int g = lane >> 2, t4 = lane & 3;
    const int lt = lane >> 3, lr8 = lane & 7;
    const int qbase = qt * 128;
    const int nkt = min(2 * qt + 26, 33);
    const int rl0 = 16 * w + g, rl1 = rl0 + 8;

    auto issue = [&](int kt, int s) {
        if (kt >= nkt) return;
        const int kb = kt * 64;
        const __half* Kb = Kg + (size_t)(b * L_TOT + kb) * D_ + h * HD_;
        const __half* Vb = Vg + (size_t)(b * L_TOT + kb) * D_ + h * HD_;
#pragma unroll
        for (int p = 0; p < 2; ++p) {
            int idx = tid + p * 256;
            int j = idx >> 3, c8 = (idx & 7) * 8;
            cp16(ks_u + (uint32_t)(s * KSB) + (uint32_t)(j * 72 + c8) * 2, Kb + (size_t)j * D_ + c8);
            cp16(vs_u + (uint32_t)(s * KSB) + (uint32_t)(j * 72 + c8) * 2, Vb + (size_t)j * D_ + c8);
        }
        if (kt < 32 && tid < 8)
            cp16(pd_u + (uint32_t)(s * 128 + tid * 16), padh + b * L_S_ + kb + tid * 8);
    };

    issue(0, 0); CP_COMMIT();
    issue(1, 1); CP_COMMIT();

    // Stage Q (fp16, pre-scaled)
#pragma unroll
    for (int p = 0; p < 4; ++p) {
        int idx = tid + p * 256;
        int row = idx >> 3, c8 = (idx & 7) * 8;
        *(uint4*)&Qs[row * 72 + c8] =
            *(const uint4*)(Qg + (size_t)(b * LQPAD + qbase + row) * D_ + h * HD_ + c8);
    }
    __syncthreads();

    uint32_t qa[4][4];
#pragma unroll
    for (int kc = 0; kc < 4; ++kc) {
        qa[kc][0] = *(const uint32_t*)&Qs[rl0 * 72 + kc * 16 + 2 * t4];
        qa[kc][1] = *(const uint32_t*)&Qs[rl1 * 72 + kc * 16 + 2 * t4];
        qa[kc][2] = *(const uint32_t*)&Qs[rl0 * 72 + kc * 16 + 2 * t4 + 8];
        qa[kc][3] = *(const uint32_t*)&Qs[rl1 * 72 + kc * 16 + 2 * t4 + 8];
    }

    float4 oacc[8];
#pragma unroll
    for (int i = 0; i < 8; ++i) oacc[i] = make_float4(0.f, 0.f, 0.f, 0.f);
    float4 lacc = make_float4(0.f, 0.f, 0.f, 0.f);

#pragma unroll 1
    for (int kt = 0; kt < nkt; ++kt) {
        const int s = kt % 3;
        __syncthreads();              // readers of stage (kt+2)%3 == (kt-1)%3 done
        issue(kt + 2, (kt + 2) % 3);
        CP_COMMIT();
        CP_WAIT2();                   // group kt complete (<=2 outstanding)

        const uint32_t ksb = ks_u + (uint32_t)(s * KSB);
        const uint32_t vsb = vs_u + (uint32_t)(s * KSB);
        const __half* ph = (const __half*)(smc + PDH_OFF + s * 128);

        // S = Q K^T (full tile)
        float4 sacc[8];
#pragma unroll
        for (int nt = 0; nt < 8; ++nt) sacc[nt] = make_float4(0.f, 0.f, 0.f, 0.f);
#pragma unroll
        for (int kc = 0; kc < 4; ++kc) {
#pragma unroll
            for (int ntp = 0; ntp < 4; ++ntp) {
                uint32_t b0, b1, b2, b3;
                uint32_t addr = ksb +
                    (uint32_t)(((ntp * 16 + (lt >> 1) * 8 + lr8) * 72) + kc * 16 + (lt & 1) * 8) * 2;
                ldsm4(b0, b1, b2, b3, addr);
                mma16(sacc[2 * ntp], qa[kc], b0, b1);
                mma16(sacc[2 * ntp + 1], qa[kc], b2, b3);
            }
        }

        // Causal mask (pad handled via V-zero + mask column)
        const int moff = kt * 64 - qbase - 1536;
        if (moff > -64) {
#pragma unroll
            for (int nt = 0; nt < 8; ++nt) {
                int j0 = nt * 8 + 2 * t4, j1 = j0 + 1;
                if (j0 + moff > rl0) sacc[nt].x = -1e30f;
                if (j1 + moff > rl0) sacc[nt].y = -1e30f;
                if (j0 + moff > rl1) sacc[nt].z = -1e30f;
                if (j1 + moff > rl1) sacc[nt].w = -1e30f;
            }
        }

        // P = exp2(S) f16x2; O += P V; l += P @ maskcol
        const bool dopad = (kt < 32);
#pragma unroll
        for (int jc = 0; jc < 4; ++jc) {
            uint32_t pa[4];
            pa[0] = h2exp2(packh2(sacc[2 * jc].x, sacc[2 * jc].y));
            pa[1] = h2exp2(packh2(sacc[2 * jc].z, sacc[2 * jc].w));
            pa[2] = h2exp2(packh2(sacc[2 * jc + 1].x, sacc[2 * jc + 1].y));
            pa[3] = h2exp2(packh2(sacc[2 * jc + 1].z, sacc[2 * jc + 1].w));
            uint32_t m0c = 0, m1c = 0;
            if (lane < 4) {
                if (dopad) {
                    m0c = *(const uint32_t*)&ph[jc * 16 + 2 * lane];
                    m1c = *(const uint32_t*)&ph[jc * 16 + 2 * lane + 8];
                } else {
                    m0c = 0x3C003C00u; m1c = 0x3C003C00u;
                }
            }
            mma16(lacc, pa, m0c, m1c);
#pragma unroll
            for (int dtp = 0; dtp < 4; ++dtp) {
                uint32_t v0, v1, v2, v3;
                uint32_t addr = vsb +
                    (uint32_t)(((jc * 16 + (lt & 1) * 8 + lr8) * 72) + (dtp * 2 + (lt >> 1)) * 8) * 2;
                ldsm4t(v0, v1, v2, v3, addr);
                mma16(oacc[2 * dtp], pa, v0, v1);
                mma16(oacc[2 * dtp + 1], pa, v2, v3);
            }
        }
    }

    float l0 = __shfl_sync(0xffffffffu, lacc.x, lane & 28);
    float l1 = __shfl_sync(0xffffffffu, lacc.z, lane & 28);

    float il0 = 1.f / l0, il1 = 1.f / l1;
#pragma unroll
    for (int dt = 0; dt < 8; ++dt) {
        int col = h * HD_ + dt * 8 + 2 * t4;
        size_t r0 = (size_t)(b * LQPAD + qbase + rl0) * D_ + col;
        size_t r1 = (size_t)(b * LQPAD + qbase + rl1) * D_ + col;
        *(__half2*)(Og + r0) = __floats2half2_rn(oacc[dt].x * il0, oacc[dt].y * il0);
        *(__half2*)(Og + r1) = __floats2half2_rn(oacc[dt].z * il1, oacc[dt].w * il1);
    }
}

// ---------------------------------------------------------------------------
extern "C" void kernel_launch(void* const* d_in, const int* in_sizes, int n_in,
                              void* d_out, int out_size) {
    const float* x     = (const float*)d_in[0];
    const int*   pad   = (const int*)d_in[1];
    const float* wq_sw = (const float*)d_in[4];
    const float* wq_sb = (const float*)d_in[5];
    const float* wq_nw = (const float*)d_in[6];
    const float* wq_nb = (const float*)d_in[7];
    const float* wk_sw = (const float*)d_in[8];
    const float* wk_sb = (const float*)d_in[9];
    const float* wk_nw = (const float*)d_in[10];
    const float* wk_nb = (const float*)d_in[11];
    const float* wv_sw = (const float*)d_in[12];
    const float* wv_sb = (const float*)d_in[13];
    const float* wv_nw = (const float*)d_in[14];
    const float* wv_nb = (const float*)d_in[15];
    const float* out_w = (const float*)d_in[16];
    const float* out_b = (const float*)d_in[17];
    float* out = (float*)d_out;

    __half *Kp, *Vp, *Qp, *Ap, *Xh, *Wh, *Ph;
    float *Pp;
    cudaGetSymbolAddress((void**)&Kp, g_K);
    cudaGetSymbolAddress((void**)&Vp, g_V);
    cudaGetSymbolAddress((void**)&Qp, g_Q);
    cudaGetSymbolAddress((void**)&Ap, g_A);
    cudaGetSymbolAddress((void**)&Pp, g_Part);
    cudaGetSymbolAddress((void**)&Xh, g_Xh);
    cudaGetSymbolAddress((void**)&Wh, g_Wh);
    cudaGetSymbolAddress((void**)&Ph, g_PadH);

    cudaFuncSetAttribute((const void*)mega_proj, cudaFuncAttributeMaxDynamicSharedMemorySize, PJ_SMEM);
    cudaFuncSetAttribute((const void*)proj_out, cudaFuncAttributeMaxDynamicSharedMemorySize, PJ_SMEM);
    cudaFuncSetAttribute((const void*)attn_mma, cudaFuncAttributeMaxDynamicSharedMemorySize, ATT_SMEM);

    prep_all<<<8448 + 1024 + 8, 256>>>(x, wk_sw, wv_sw, wq_sw, out_w, pad, Xh, Wh, Ph);

    mega_proj<<<1536, 256, PJ_SMEM>>>(Xh, x, Wh, wk_sb, wv_sb, wq_sb,
                                      wk_nw, wv_nw, wq_nw, pad, Kp, Vp, Qp, Pp);
    ns_reduce_all<<<dim3(64, 3), 512>>>(Pp, wk_nb, wv_nb, wq_nb, Kp, Vp, Qp);

    attn_mma<<<320, 256, ATT_SMEM>>>(Qp, Kp, Vp, Ph, Ap);

    proj_out<<<dim3(36, 4), 256, PJ_SMEM>>>(Ap, Wh + 3 * WSZ, out_b, out);
}